// round 16
// baseline (speedup 1.0000x reference)
#include <cuda_runtime.h>
#include <cuda_bf16.h>
#include <cuda_fp16.h>
#include <cstdint>

#define NUM_B 2
#define SEQ   2048
#define HD    64
#define NH    12
#define NEGV  (-99999.0f)
#define TOT   (NUM_B*NH*SEQ*HD)
#define N_PAIRS 384        // (qx, bh) base items
#define N_ITEMS (2*N_PAIRS)
#define N_CTAS  296

// ---- cp.async ----
__device__ __forceinline__ void cp16(void* smem_dst, const void* gmem_src) {
    unsigned s = (unsigned)__cvta_generic_to_shared(smem_dst);
    asm volatile("cp.async.ca.shared.global [%0], [%1], 16;\n" :: "r"(s), "l"(gmem_src));
}
__device__ __forceinline__ void cp_commit() { asm volatile("cp.async.commit_group;\n"); }
__device__ __forceinline__ void cp_wait0()  { asm volatile("cp.async.wait_group 0;\n" ::: "memory"); }

__device__ __forceinline__ uint32_t smem_u32(const void* p) {
    uint32_t a;
    asm("{ .reg .u64 t; cvta.to.shared.u64 t, %1; cvt.u32.u64 %0, t; }" : "=r"(a) : "l"(p));
    return a;
}

// ---- warp MMA primitives ----
__device__ __forceinline__ void mma16816(float* d, const uint32_t* a, uint32_t b0, uint32_t b1) {
    asm volatile("mma.sync.aligned.m16n8k16.row.col.f32.bf16.bf16.f32 "
                 "{%0,%1,%2,%3}, {%4,%5,%6,%7}, {%8,%9}, {%0,%1,%2,%3};"
                 : "+f"(d[0]), "+f"(d[1]), "+f"(d[2]), "+f"(d[3])
                 : "r"(a[0]), "r"(a[1]), "r"(a[2]), "r"(a[3]), "r"(b0), "r"(b1));
}
__device__ __forceinline__ void mmah(float* d, const uint32_t* a, uint32_t b0, uint32_t b1) {
    asm volatile("mma.sync.aligned.m16n8k16.row.col.f32.f16.f16.f32 "
                 "{%0,%1,%2,%3}, {%4,%5,%6,%7}, {%8,%9}, {%0,%1,%2,%3};"
                 : "+f"(d[0]), "+f"(d[1]), "+f"(d[2]), "+f"(d[3])
                 : "r"(a[0]), "r"(a[1]), "r"(a[2]), "r"(a[3]), "r"(b0), "r"(b1));
}
__device__ __forceinline__ void ldx4(uint32_t* r, uint32_t addr) {
    asm volatile("ldmatrix.sync.aligned.m8n8.x4.shared.b16 {%0,%1,%2,%3}, [%4];"
                 : "=r"(r[0]), "=r"(r[1]), "=r"(r[2]), "=r"(r[3]) : "r"(addr));
}
__device__ __forceinline__ void ldx4t(uint32_t* r, uint32_t addr) {
    asm volatile("ldmatrix.sync.aligned.m8n8.x4.trans.shared.b16 {%0,%1,%2,%3}, [%4];"
                 : "=r"(r[0]), "=r"(r[1]), "=r"(r[2]), "=r"(r[3]) : "r"(addr));
}

// ---- bf16 pack ----
__device__ __forceinline__ uint32_t packbf2(__nv_bfloat16 a, __nv_bfloat16 b) {
    __nv_bfloat162 t; t.x = a; t.y = b; return *reinterpret_cast<uint32_t*>(&t);
}
__device__ __forceinline__ uint32_t pack_hi(float a, float b) {
    return packbf2(__float2bfloat16_rn(a), __float2bfloat16_rn(b));
}
__device__ __forceinline__ uint32_t pack_lo(float a, float b, uint32_t hi) {
    __nv_bfloat162 h = *reinterpret_cast<__nv_bfloat162*>(&hi);
    return packbf2(__float2bfloat16_rn(a - __bfloat162float(h.x)),
                   __float2bfloat16_rn(b - __bfloat162float(h.y)));
}
// ---- fp16 pack (Q/K path only; values O(1), range-safe) ----
__device__ __forceinline__ uint32_t packh2(float a, float b) {
    __half2 t = __floats2half2_rn(a, b);
    return *reinterpret_cast<uint32_t*>(&t);
}
__device__ __forceinline__ uint32_t packh2_lo(float a, float b, uint32_t hi) {
    __half2 h = *reinterpret_cast<__half2*>(&hi);
    return packh2(a - __half2float(h.x), b - __half2float(h.y));
}

// ---- global scratch ----
__device__ __align__(16) __half g_Q[TOT];           // fp16 single
__device__ __align__(16) __half g_Kh[TOT];          // fp16 hi
__device__ __align__(16) __half g_Kl[TOT];          // fp16 lo
__device__ __align__(16) __nv_bfloat16 g_Vh[TOT];   // bf16 hi
__device__ __align__(16) __nv_bfloat16 g_Vl[TOT];   // bf16 lo
__device__ __align__(16) __nv_bfloat16 g_Ohi[TOT];
__device__ __align__(16) __nv_bfloat16 g_Olo[TOT];
__device__ __align__(16) __nv_bfloat16 g_Woh[768*64];
__device__ __align__(16) __nv_bfloat16 g_Wol[768*64];
// split-K partials (half A -> half B)
__device__ __align__(16) float g_Pacc[N_PAIRS*128*64];
__device__ float g_Plsum[N_PAIRS*128];
__device__ int   g_flag[N_PAIRS];
__device__ int   g_done[NUM_B*16];   // per (bi,qx) head-completion counters
__device__ int   g_counter;

#define STRB 144   // 16-bit row stride bytes (64 vals + pad)

// ---------------------------------------------------------------------------
// Kernel 0: prep — split Wo into bf16 hi/lo, reset counters + flags.
// ---------------------------------------------------------------------------
__global__ __launch_bounds__(256) void prep_kernel(const float* __restrict__ Wo)
{
    const int i = blockIdx.x*256 + threadIdx.x;
    if (i == 0) g_counter = 0;
    if (i < N_PAIRS) g_flag[i] = 0;
    if (i < NUM_B*16) g_done[i] = 0;
    float4 v = reinterpret_cast<const float4*>(Wo)[i];
    uint32_t h01 = pack_hi(v.x, v.y), h23 = pack_hi(v.z, v.w);
    uint32_t l01 = pack_lo(v.x, v.y, h01), l23 = pack_lo(v.z, v.w, h23);
    *reinterpret_cast<uint2*>(g_Woh + i*4) = make_uint2(h01, h23);
    *reinterpret_cast<uint2*>(g_Wol + i*4) = make_uint2(l01, l23);
}

// ---------------------------------------------------------------------------
// Kernel 1: HMMA fused QKV projection (bf16 3-term internally).
// Outputs: Q fp16 single, K fp16 hi/lo, V bf16 hi/lo.  (R12, unchanged)
// ---------------------------------------------------------------------------
#define QK2_XH 0
#define QK2_XL (64*STRB)
#define QK2_WB (2*64*STRB)
#define QKV2_SMEM (QK2_WB + 6*64*STRB)

__global__ __launch_bounds__(128) void qkv_kernel(
    const float* __restrict__ x,
    const float* __restrict__ Wq, const float* __restrict__ bq,
    const float* __restrict__ Wk, const float* __restrict__ bk,
    const float* __restrict__ Wv, const float* __restrict__ bv)
{
    extern __shared__ __align__(16) char smn[];
    const uint32_t sb = smem_u32(smn);
    const int tile = blockIdx.x;
    const int head = blockIdx.y;
    const int tid  = threadIdx.x;
    const int wid  = tid >> 5;
    const int lane = tid & 31;
    const int g    = lane >> 2;
    const int t    = lane & 3;
    const int qrow_l = lane & 15;
    const int qch    = lane >> 4;
    const int vrow_l = ((lane >> 3) & 1)*8 + (lane & 7);
    const int vch    = (lane >> 4) & 1;

    #pragma unroll
    for (int i = tid; i < 1024; i += 128) {
        const int r = i >> 4, c4 = (i & 15) << 2;
        float4 v = *reinterpret_cast<const float4*>(x + (tile*64 + r)*64 + c4);
        uint32_t h01 = pack_hi(v.x, v.y), h23 = pack_hi(v.z, v.w);
        uint32_t l01 = pack_lo(v.x, v.y, h01), l23 = pack_lo(v.z, v.w, h23);
        *reinterpret_cast<uint2*>(smn + QK2_XH + r*STRB + c4*2) = make_uint2(h01, h23);
        *reinterpret_cast<uint2*>(smn + QK2_XL + r*STRB + c4*2) = make_uint2(l01, l23);
    }
    {
        const float* const Wm[3] = {Wq, Wk, Wv};
        #pragma unroll
        for (int m = 0; m < 3; m++) {
            const float* W = Wm[m];
            const int base = QK2_WB + m*(2*64*STRB);
            #pragma unroll
            for (int i = tid; i < 1024; i += 128) {
                const int r = i >> 4, c4 = (i & 15) << 2;
                float4 v = *reinterpret_cast<const float4*>(W + r*768 + head*64 + c4);
                uint32_t h01 = pack_hi(v.x, v.y), h23 = pack_hi(v.z, v.w);
                uint32_t l01 = pack_lo(v.x, v.y, h01), l23 = pack_lo(v.z, v.w, h23);
                *reinterpret_cast<uint2*>(smn + base + r*STRB + c4*2) = make_uint2(h01, h23);
                *reinterpret_cast<uint2*>(smn + base + 64*STRB + r*STRB + c4*2) = make_uint2(l01, l23);
            }
        }
    }
    __syncthreads();

    uint32_t ah[4][4], al[4][4];
    #pragma unroll
    for (int kc = 0; kc < 4; kc++) {
        const uint32_t aoff = (uint32_t)((wid*16 + qrow_l)*STRB + (kc*16 + qch*8)*2);
        ldx4(ah[kc], sb + QK2_XH + aoff);
        ldx4(al[kc], sb + QK2_XL + aoff);
    }

    const int rg0 = tile*64 + wid*16 + g;
    const int bi  = rg0 >> 11;
    const int si0 = rg0 & (SEQ-1);
    const int bh  = bi*NH + head;
    const float* const Bm[3] = {bq, bk, bv};

    #pragma unroll
    for (int m = 0; m < 3; m++) {
        const uint32_t whb = sb + QK2_WB + m*(2*64*STRB);
        const uint32_t wlb = whb + 64*STRB;
        float dacc[8][4];
        #pragma unroll
        for (int j = 0; j < 8; j++)
            #pragma unroll
            for (int e = 0; e < 4; e++) dacc[j][e] = 0.f;

        #pragma unroll
        for (int kc = 0; kc < 4; kc++) {
            #pragma unroll
            for (int jdp = 0; jdp < 4; jdp++) {
                const uint32_t voff = (uint32_t)((kc*16 + vrow_l)*STRB + ((2*jdp + vch)*8)*2);
                uint32_t bhf[4], blf[4];
                ldx4t(bhf, whb + voff);
                ldx4t(blf, wlb + voff);
                mma16816(dacc[2*jdp],   ah[kc], bhf[0], bhf[1]);
                mma16816(dacc[2*jdp+1], ah[kc], bhf[2], bhf[3]);
                mma16816(dacc[2*jdp],   ah[kc], blf[0], blf[1]);
                mma16816(dacc[2*jdp+1], ah[kc], blf[2], blf[3]);
                mma16816(dacc[2*jdp],   al[kc], bhf[0], bhf[1]);
                mma16816(dacc[2*jdp+1], al[kc], bhf[2], bhf[3]);
            }
        }

        const float* bias = Bm[m] + head*64;
        #pragma unroll
        for (int jd = 0; jd < 8; jd++) {
            const int col = jd*8 + 2*t;
            const float b0 = bias[col], b1 = bias[col+1];
            const float v0 = dacc[jd][0] + b0, v1 = dacc[jd][1] + b1;
            const float v2 = dacc[jd][2] + b0, v3 = dacc[jd][3] + b1;
            const int idx0 = (bh*SEQ + si0)*HD + col;
            const int idx8 = idx0 + 8*HD;
            if (m == 0) {
                *reinterpret_cast<uint32_t*>(g_Q + idx0) = packh2(v0, v1);
                *reinterpret_cast<uint32_t*>(g_Q + idx8) = packh2(v2, v3);
            } else if (m == 1) {
                uint32_t h01 = packh2(v0, v1), h23 = packh2(v2, v3);
                *reinterpret_cast<uint32_t*>(g_Kh + idx0) = h01;
                *reinterpret_cast<uint32_t*>(g_Kl + idx0) = packh2_lo(v0, v1, h01);
                *reinterpret_cast<uint32_t*>(g_Kh + idx8) = h23;
                *reinterpret_cast<uint32_t*>(g_Kl + idx8) = packh2_lo(v2, v3, h23);
            } else {
                uint32_t h01 = pack_hi(v0, v1), h23 = pack_hi(v2, v3);
                *reinterpret_cast<uint32_t*>(g_Vh + idx0) = h01;
                *reinterpret_cast<uint32_t*>(g_Vl + idx0) = pack_lo(v0, v1, h01);
                *reinterpret_cast<uint32_t*>(g_Vh + idx8) = h23;
                *reinterpret_cast<uint32_t*>(g_Vl + idx8) = pack_lo(v2, v3, h23);
            }
        }
    }
}

// ---------------------------------------------------------------------------
// Kernel 2: flash attention with SPLIT-K + FUSED OUTPUT PROJECTION.
// After the 12th head of a (bi,qx) block completes, the finishing CTA runs
// the projection for those 128 rows in-place (streaming heads, fixed order).
// ---------------------------------------------------------------------------
#define SM_ITEM 0
#define SM_Q    16
#define SM_KH0  (SM_Q + 128*STRB)
#define SM_KL0  (SM_KH0 + 64*STRB)
#define SM_VH0  (SM_KL0 + 64*STRB)
#define SM_VL0  (SM_VH0 + 64*STRB)
#define SM_KH1  (SM_VL0 + 64*STRB)
#define SM_KL1  (SM_KH1 + 64*STRB)
#define SM_VH1  (SM_KL1 + 64*STRB)
#define SM_VL1  (SM_VH1 + 64*STRB)
#define ATTN_SMEM_BYTES (SM_VL1 + 64*STRB)
// fused-proj smem overlay (reuses attention tiles region)
#define PF_OH  16
#define PF_OL  (PF_OH + 128*STRB)
#define PF_WH  (PF_OL + 128*STRB)
#define PF_WL  (PF_WH + 64*STRB)

__global__ __launch_bounds__(256, 2) void attn_kernel(
    const float* __restrict__ bo, float* __restrict__ out)
{
    extern __shared__ __align__(16) char smn[];
    const uint32_t sb = smem_u32(smn);
    const int tid  = threadIdx.x;
    const int wid  = tid >> 5;
    const int lane = tid & 31;
    const int g    = lane >> 2;
    const int t    = lane & 3;
    int* itp = reinterpret_cast<int*>(smn + SM_ITEM);
    int* dnp = itp + 1;

    const int qrow_l = (lane & 15);
    const int qch    = (lane >> 4);
    const int krow_l = ((lane >> 4) & 1)*8 + (lane & 7);
    const int kch    = (lane >> 3) & 1;
    const int vrow_l = ((lane >> 3) & 1)*8 + (lane & 7);
    const int vch    = (lane >> 4) & 1;

    for (;;) {
        __syncthreads();
        if (tid == 0) *itp = atomicAdd(&g_counter, 1);
        __syncthreads();
        const int it = *itp;
        if (it >= N_ITEMS) return;

        const int p    = it >> 1;
        const int half = it & 1;
        const int qr = p / 24;
        const int qx = 15 - qr;
        const int bh = p - qr * 24;
        const int bi = bh / NH;
        const int qb  = qx * 128;
        const int off = bh * SEQ * HD;
        const int nkt = 2*qx + 2;
        const int nA  = nkt >> 1;
        const int kt0 = half ? nA  : 0;
        const int kt1 = half ? nkt : nA;
        const int slot = p;

        #pragma unroll
        for (int i = tid; i < 1024; i += 256) {
            const int r = i >> 3, c = i & 7;
            cp16(smn + SM_Q + r*STRB + c*16, g_Q + off + (qb + r)*64 + c*8);
        }
        {
            const int kb0 = kt0 * 64;
            #pragma unroll
            for (int i = tid; i < 512; i += 256) {
                const int r = i >> 3, c = i & 7;
                cp16(smn + SM_KH0 + r*STRB + c*16, g_Kh + off + (kb0 + r)*64 + c*8);
                cp16(smn + SM_KL0 + r*STRB + c*16, g_Kl + off + (kb0 + r)*64 + c*8);
                cp16(smn + SM_VH0 + r*STRB + c*16, g_Vh + off + (kb0 + r)*64 + c*8);
                cp16(smn + SM_VL0 + r*STRB + c*16, g_Vl + off + (kb0 + r)*64 + c*8);
            }
        }
        cp_commit();

        float dacc[8][4];
        #pragma unroll
        for (int j = 0; j < 8; j++)
            #pragma unroll
            for (int e = 0; e < 4; e++) dacc[j][e] = 0.f;
        float lsum0 = 0.f, lsum8 = 0.f;

        const int row0 = qb + wid*16 + g;
        const int row8 = row0 + 8;

        for (int kt = kt0; kt < kt1; ++kt) {
            const int kb  = kt * 64;
            const int buf = (kt - kt0) & 1;
            cp_wait0();
            __syncthreads();

            if (kt + 1 < kt1) {
                const int nkb = kb + 64;
                const uint32_t okh = buf ? SM_KH0 : SM_KH1;
                const uint32_t okl = buf ? SM_KL0 : SM_KL1;
                const uint32_t ovh = buf ? SM_VH0 : SM_VH1;
                const uint32_t ovl = buf ? SM_VL0 : SM_VL1;
                #pragma unroll
                for (int i = tid; i < 512; i += 256) {
                    const int r = i >> 3, c = i & 7;
                    cp16(smn + okh + r*STRB + c*16, g_Kh + off + (nkb + r)*64 + c*8);
                    cp16(smn + okl + r*STRB + c*16, g_Kl + off + (nkb + r)*64 + c*8);
                    cp16(smn + ovh + r*STRB + c*16, g_Vh + off + (nkb + r)*64 + c*8);
                    cp16(smn + ovl + r*STRB + c*16, g_Vl + off + (nkb + r)*64 + c*8);
                }
            }
            cp_commit();

            const uint32_t bkh = sb + (buf ? SM_KH1 : SM_KH0);
            const uint32_t bkl = sb + (buf ? SM_KL1 : SM_KL0);
            const uint32_t bvh = sb + (buf ? SM_VH1 : SM_VH0);
            const uint32_t bvl = sb + (buf ? SM_VL1 : SM_VL0);

            float sacc[8][4];
            #pragma unroll
            for (int j = 0; j < 8; j++)
                #pragma unroll
                for (int e = 0; e < 4; e++) sacc[j][e] = 0.f;

            #pragma unroll
            for (int ks = 0; ks < 4; ks++) {
                uint32_t qh[4];
                const uint32_t qoff = (uint32_t)((wid*16 + qrow_l)*STRB + (ks*16 + qch*8)*2);
                ldx4(qh, sb + SM_Q + qoff);
                #pragma unroll
                for (int jp = 0; jp < 4; jp++) {
                    const uint32_t koff = (uint32_t)((jp*16 + krow_l)*STRB + (ks*16 + kch*8)*2);
                    uint32_t khb[4], klb[4];
                    ldx4(khb, bkh + koff);
                    ldx4(klb, bkl + koff);
                    mmah(sacc[2*jp],   qh, khb[0], khb[1]);
                    mmah(sacc[2*jp+1], qh, khb[2], khb[3]);
                    mmah(sacc[2*jp],   qh, klb[0], klb[1]);
                    mmah(sacc[2*jp+1], qh, klb[2], klb[3]);
                }
            }

            uint32_t ph[4][4], pl[4][4];
            #pragma unroll
            for (int jn = 0; jn < 8; jn++) {
                const int col = kb + jn*8 + 2*t;
                float v0 = sacc[jn][0], v1 = sacc[jn][1];
                float v2 = sacc[jn][2], v3 = sacc[jn][3];
                if (col     > row0 || v0 == 0.0f) v0 = NEGV;
                if (col + 1 > row0 || v1 == 0.0f) v1 = NEGV;
                if (col     > row8 || v2 == 0.0f) v2 = NEGV;
                if (col + 1 > row8 || v3 == 0.0f) v3 = NEGV;
                const float p0 = __expf(v0);
                const float p1 = __expf(v1);
                const float p2 = __expf(v2);
                const float p3 = __expf(v3);
                lsum0 += p0 + p1;
                lsum8 += p2 + p3;
                const int kc = jn >> 1, hf = jn & 1;
                uint32_t h01 = pack_hi(p0, p1);
                uint32_t h23 = pack_hi(p2, p3);
                ph[kc][hf*2 + 0] = h01;
                ph[kc][hf*2 + 1] = h23;
                pl[kc][hf*2 + 0] = pack_lo(p0, p1, h01);
                pl[kc][hf*2 + 1] = pack_lo(p2, p3, h23);
            }

            #pragma unroll
            for (int kc = 0; kc < 4; kc++) {
                #pragma unroll
                for (int jdp = 0; jdp < 4; jdp++) {
                    const uint32_t voff =
                        (uint32_t)((kc*16 + vrow_l)*STRB + ((2*jdp + vch)*8)*2);
                    uint32_t vhb[4], vlb[4];
                    ldx4t(vhb, bvh + voff);
                    ldx4t(vlb, bvl + voff);
                    mma16816(dacc[2*jdp],   ph[kc], vhb[0], vhb[1]);
                    mma16816(dacc[2*jdp+1], ph[kc], vhb[2], vhb[3]);
                    mma16816(dacc[2*jdp],   ph[kc], vlb[0], vlb[1]);
                    mma16816(dacc[2*jdp+1], ph[kc], vlb[2], vlb[3]);
                    mma16816(dacc[2*jdp],   pl[kc], vhb[0], vhb[1]);
                    mma16816(dacc[2*jdp+1], pl[kc], vhb[2], vhb[3]);
                }
            }
        }

        // ---- quad-reduce this half's row sums ----
        #pragma unroll
        for (int o_ = 1; o_ < 4; o_ <<= 1) {
            lsum0 += __shfl_xor_sync(0xffffffffu, lsum0, o_);
            lsum8 += __shfl_xor_sync(0xffffffffu, lsum8, o_);
        }
        const int rloc0 = wid*16 + g;
        const int rloc8 = rloc0 + 8;
        float* pacc = g_Pacc + slot*(128*64);

        if (half == 0) {
            #pragma unroll
            for (int jd = 0; jd < 8; jd++) {
                const int col = jd*8 + 2*t;
                *reinterpret_cast<float2*>(pacc + rloc0*64 + col) =
                    make_float2(dacc[jd][0], dacc[jd][1]);
                *reinterpret_cast<float2*>(pacc + rloc8*64 + col) =
                    make_float2(dacc[jd][2], dacc[jd][3]);
            }
            if (t == 0) {
                g_Plsum[slot*128 + rloc0] = lsum0;
                g_Plsum[slot*128 + rloc8] = lsum8;
            }
            __threadfence();
            __syncthreads();
            if (tid == 0) atomicExch(&g_flag[slot], 1);
            continue;
        }

        // half B: wait for A, merge, normalize, store O
        if (tid == 0) { while (atomicAdd(&g_flag[slot], 0) == 0) { } }
        __syncthreads();
        __threadfence();
        lsum0 += g_Plsum[slot*128 + rloc0];
        lsum8 += g_Plsum[slot*128 + rloc8];
        const float inv0 = 1.0f / lsum0;
        const float inv8 = 1.0f / lsum8;
        #pragma unroll
        for (int jd = 0; jd < 8; jd++) {
            const int col = jd*8 + 2*t;
            float2 a0 = *reinterpret_cast<float2*>(pacc + rloc0*64 + col);
            float2 a8 = *reinterpret_cast<float2*>(pacc + rloc8*64 + col);
            const float v0 = (dacc[jd][0] + a0.x)*inv0;
            const float v1 = (dacc[jd][1] + a0.y)*inv0;
            const float v2 = (dacc[jd][2] + a8.x)*inv8;
            const float v3 = (dacc[jd][3] + a8.y)*inv8;
            uint32_t h01 = pack_hi(v0, v1), l01 = pack_lo(v0, v1, h01);
            uint32_t h23 = pack_hi(v2, v3), l23 = pack_lo(v2, v3, h23);
            *reinterpret_cast<uint32_t*>(g_Ohi + off + row0*64 + col) = h01;
            *reinterpret_cast<uint32_t*>(g_Olo + off + row0*64 + col) = l01;
            *reinterpret_cast<uint32_t*>(g_Ohi + off + row8*64 + col) = h23;
            *reinterpret_cast<uint32_t*>(g_Olo + off + row8*64 + col) = l23;
        }

        // ---- head-completion counter; last head runs the fused projection ----
        __threadfence();
        __syncthreads();
        if (tid == 0) *dnp = atomicAdd(&g_done[bi*16 + qx], 1);
        __syncthreads();
        if (*dnp != NH - 1) continue;
        __threadfence();

        // === fused output projection for rows [qb, qb+128) of batch bi ===
        {
            float pacc2[8][4];
            #pragma unroll
            for (int j = 0; j < 8; j++)
                #pragma unroll
                for (int e = 0; e < 4; e++) pacc2[j][e] = 0.f;

            for (int h = 0; h < NH; ++h) {
                __syncthreads();   // previous head's smem fully consumed
                const int obh = bi*NH + h;
                #pragma unroll
                for (int i = tid; i < 1024; i += 256) {
                    const int r = i >> 3, c = i & 7;
                    const int gidx = (obh*SEQ + qb + r)*64 + c*8;
                    cp16(smn + PF_OH + r*STRB + c*16, g_Ohi + gidx);
                    cp16(smn + PF_OL + r*STRB + c*16, g_Olo + gidx);
                }
                #pragma unroll
                for (int i = tid; i < 512; i += 256) {
                    const int r = i >> 3, c = i & 7;
                    cp16(smn + PF_WH + r*STRB + c*16, g_Woh + (h*64 + r)*64 + c*8);
                    cp16(smn + PF_WL + r*STRB + c*16, g_Wol + (h*64 + r)*64 + c*8);
                }
                cp_commit();
                cp_wait0();
                __syncthreads();

                #pragma unroll
                for (int kc = 0; kc < 4; kc++) {
                    uint32_t ah[4], al[4];
                    const uint32_t aoff =
                        (uint32_t)((wid*16 + qrow_l)*STRB + (kc*16 + qch*8)*2);
                    ldx4(ah, sb + PF_OH + aoff);
                    ldx4(al, sb + PF_OL + aoff);
                    #pragma unroll
                    for (int jdp = 0; jdp < 4; jdp++) {
                        const uint32_t voff =
                            (uint32_t)((kc*16 + vrow_l)*STRB + ((2*jdp + vch)*8)*2);
                        uint32_t bhf[4], blf[4];
                        ldx4t(bhf, sb + PF_WH + voff);
                        ldx4t(blf, sb + PF_WL + voff);
                        mma16816(pacc2[2*jdp],   ah, bhf[0], bhf[1]);
                        mma16816(pacc2[2*jdp+1], ah, bhf[2], bhf[3]);
                        mma16816(pacc2[2*jdp],   ah, blf[0], blf[1]);
                        mma16816(pacc2[2*jdp+1], ah, blf[2], blf[3]);
                        mma16816(pacc2[2*jdp],   al, bhf[0], bhf[1]);
                        mma16816(pacc2[2*jdp+1], al, bhf[2], bhf[3]);
                    }
                }
            }

            const int orow0 = bi*SEQ + qb + wid*16 + g;
            const int orow8 = orow0 + 8;
            #pragma unroll
            for (int jd = 0; jd < 8; jd++) {
                const int col = jd*8 + 2*t;
                const float b0 = bo[col], b1 = bo[col+1];
                *reinterpret_cast<float2*>(out + orow0*64 + col) =
                    make_float2(pacc2[jd][0] + b0, pacc2[jd][1] + b1);
                *reinterpret_cast<float2*>(out + orow8*64 + col) =
                    make_float2(pacc2[jd][2] + b0, pacc2[jd][3] + b1);
            }
        }
    }
}

// ---------------------------------------------------------------------------
extern "C" void kernel_launch(void* const* d_in, const int* in_sizes, int n_in,
                              void* d_out, int out_size)
{
    (void)in_sizes; (void)n_in; (void)out_size;
    const float* x  = (const float*)d_in[0];
    const float* Wq = (const float*)d_in[1];
    const float* bq = (const float*)d_in[2];
    const float* Wk = (const float*)d_in[3];
    const float* bk = (const float*)d_in[4];
    const float* Wv = (const float*)d_in[5];
    const float* bv = (const float*)d_in[6];
    const float* Wo = (const float*)d_in[7];
    const float* bo = (const float*)d_in[8];
    float* out = (float*)d_out;

    cudaFuncSetAttribute(attn_kernel,
                         cudaFuncAttributeMaxDynamicSharedMemorySize,
                         ATTN_SMEM_BYTES);
    cudaFuncSetAttribute(qkv_kernel,
                         cudaFuncAttributeMaxDynamicSharedMemorySize,
                         QKV2_SMEM);

    prep_kernel<<<48, 256>>>(Wo);
    qkv_kernel<<<dim3(64, 12), 128, QKV2_SMEM>>>(x, Wq, bq, Wk, bk, Wv, bv);
    attn_kernel<<<N_CTAS, 256, ATTN_SMEM_BYTES>>>(bo, out);
}

// round 17
// speedup vs baseline: 1.1356x; 1.1356x over previous
#include <cuda_runtime.h>
#include <cuda_bf16.h>
#include <cuda_fp16.h>
#include <cstdint>

#define NUM_B 2
#define SEQ   2048
#define HD    64
#define NH    12
#define NEGV  (-99999.0f)
#define TOT   (NUM_B*NH*SEQ*HD)
#define N_PAIRS 384        // (qx, bh) base items
#define N_ITEMS (2*N_PAIRS)
#define N_CTAS  296

// ---- cp.async ----
__device__ __forceinline__ void cp16(void* smem_dst, const void* gmem_src) {
    unsigned s = (unsigned)__cvta_generic_to_shared(smem_dst);
    asm volatile("cp.async.ca.shared.global [%0], [%1], 16;\n" :: "r"(s), "l"(gmem_src));
}
__device__ __forceinline__ void cp_commit() { asm volatile("cp.async.commit_group;\n"); }
__device__ __forceinline__ void cp_wait0()  { asm volatile("cp.async.wait_group 0;\n" ::: "memory"); }

__device__ __forceinline__ uint32_t smem_u32(const void* p) {
    uint32_t a;
    asm("{ .reg .u64 t; cvta.to.shared.u64 t, %1; cvt.u32.u64 %0, t; }" : "=r"(a) : "l"(p));
    return a;
}

// ---- warp MMA primitives ----
__device__ __forceinline__ void mma16816(float* d, const uint32_t* a, uint32_t b0, uint32_t b1) {
    asm volatile("mma.sync.aligned.m16n8k16.row.col.f32.bf16.bf16.f32 "
                 "{%0,%1,%2,%3}, {%4,%5,%6,%7}, {%8,%9}, {%0,%1,%2,%3};"
                 : "+f"(d[0]), "+f"(d[1]), "+f"(d[2]), "+f"(d[3])
                 : "r"(a[0]), "r"(a[1]), "r"(a[2]), "r"(a[3]), "r"(b0), "r"(b1));
}
__device__ __forceinline__ void mmah(float* d, const uint32_t* a, uint32_t b0, uint32_t b1) {
    asm volatile("mma.sync.aligned.m16n8k16.row.col.f32.f16.f16.f32 "
                 "{%0,%1,%2,%3}, {%4,%5,%6,%7}, {%8,%9}, {%0,%1,%2,%3};"
                 : "+f"(d[0]), "+f"(d[1]), "+f"(d[2]), "+f"(d[3])
                 : "r"(a[0]), "r"(a[1]), "r"(a[2]), "r"(a[3]), "r"(b0), "r"(b1));
}
__device__ __forceinline__ void ldx4(uint32_t* r, uint32_t addr) {
    asm volatile("ldmatrix.sync.aligned.m8n8.x4.shared.b16 {%0,%1,%2,%3}, [%4];"
                 : "=r"(r[0]), "=r"(r[1]), "=r"(r[2]), "=r"(r[3]) : "r"(addr));
}
__device__ __forceinline__ void ldx4t(uint32_t* r, uint32_t addr) {
    asm volatile("ldmatrix.sync.aligned.m8n8.x4.trans.shared.b16 {%0,%1,%2,%3}, [%4];"
                 : "=r"(r[0]), "=r"(r[1]), "=r"(r[2]), "=r"(r[3]) : "r"(addr));
}

// ---- bf16 pack ----
__device__ __forceinline__ uint32_t packbf2(__nv_bfloat16 a, __nv_bfloat16 b) {
    __nv_bfloat162 t; t.x = a; t.y = b; return *reinterpret_cast<uint32_t*>(&t);
}
__device__ __forceinline__ uint32_t pack_hi(float a, float b) {
    return packbf2(__float2bfloat16_rn(a), __float2bfloat16_rn(b));
}
__device__ __forceinline__ uint32_t pack_lo(float a, float b, uint32_t hi) {
    __nv_bfloat162 h = *reinterpret_cast<__nv_bfloat162*>(&hi);
    return packbf2(__float2bfloat16_rn(a - __bfloat162float(h.x)),
                   __float2bfloat16_rn(b - __bfloat162float(h.y)));
}
// ---- fp16 pack (Q/K path only; values O(1), range-safe) ----
__device__ __forceinline__ uint32_t packh2(float a, float b) {
    __half2 t = __floats2half2_rn(a, b);
    return *reinterpret_cast<uint32_t*>(&t);
}
__device__ __forceinline__ uint32_t packh2_lo(float a, float b, uint32_t hi) {
    __half2 h = *reinterpret_cast<__half2*>(&hi);
    return packh2(a - __half2float(h.x), b - __half2float(h.y));
}

// ---- global scratch ----
__device__ __align__(16) __half g_Q[TOT];           // fp16 single
__device__ __align__(16) __half g_Kh[TOT];          // fp16 hi
__device__ __align__(16) __half g_Kl[TOT];          // fp16 lo
__device__ __align__(16) __nv_bfloat16 g_Vh[TOT];   // bf16 hi
__device__ __align__(16) __nv_bfloat16 g_Vl[TOT];   // bf16 lo
__device__ __align__(16) __nv_bfloat16 g_Ohi[TOT];
__device__ __align__(16) __nv_bfloat16 g_Olo[TOT];
__device__ __align__(16) __nv_bfloat16 g_Woh[768*64];
__device__ __align__(16) __nv_bfloat16 g_Wol[768*64];
// split-K partials (half A -> half B)
__device__ __align__(16) float g_Pacc[N_PAIRS*128*64];
__device__ float g_Plsum[N_PAIRS*128];
__device__ int   g_flag[N_PAIRS];
__device__ int   g_counter;

#define STRB 144   // 16-bit row stride bytes (64 vals + pad)

// ---------------------------------------------------------------------------
// Kernel 1: HMMA fused QKV projection (bf16 3-term internally).
// Also absorbs the old prep kernel: Wo hi/lo split (16 float4 per CTA) and
// counter/flag resets happen at entry, before attn launches.
// Outputs: Q fp16 single, K fp16 hi/lo, V bf16 hi/lo.
// ---------------------------------------------------------------------------
#define QK2_XH 0
#define QK2_XL (64*STRB)
#define QK2_WB (2*64*STRB)
#define QKV2_SMEM (QK2_WB + 6*64*STRB)

__global__ __launch_bounds__(128) void qkv_kernel(
    const float* __restrict__ x,
    const float* __restrict__ Wq, const float* __restrict__ bq,
    const float* __restrict__ Wk, const float* __restrict__ bk,
    const float* __restrict__ Wv, const float* __restrict__ bv,
    const float* __restrict__ Wo)
{
    extern __shared__ __align__(16) char smn[];
    const uint32_t sb = smem_u32(smn);
    const int tile = blockIdx.x;
    const int head = blockIdx.y;
    const int lb   = head*64 + tile;     // linear block id 0..767
    const int tid  = threadIdx.x;
    const int wid  = tid >> 5;
    const int lane = tid & 31;
    const int g    = lane >> 2;
    const int t    = lane & 3;
    const int qrow_l = lane & 15;
    const int qch    = lane >> 4;
    const int vrow_l = ((lane >> 3) & 1)*8 + (lane & 7);
    const int vch    = (lane >> 4) & 1;

    // ---- absorbed prep work (parallel across 768 CTAs) ----
    if (tid == 0) {
        if (lb == 0) g_counter = 0;
        if (lb < N_PAIRS) g_flag[lb] = 0;
    }
    if (tid < 16) {
        const int i = lb*16 + tid;       // 0..12287 float4 groups of Wo
        float4 v = reinterpret_cast<const float4*>(Wo)[i];
        uint32_t h01 = pack_hi(v.x, v.y), h23 = pack_hi(v.z, v.w);
        uint32_t l01 = pack_lo(v.x, v.y, h01), l23 = pack_lo(v.z, v.w, h23);
        *reinterpret_cast<uint2*>(g_Woh + i*4) = make_uint2(h01, h23);
        *reinterpret_cast<uint2*>(g_Wol + i*4) = make_uint2(l01, l23);
    }

    #pragma unroll
    for (int i = tid; i < 1024; i += 128) {
        const int r = i >> 4, c4 = (i & 15) << 2;
        float4 v = *reinterpret_cast<const float4*>(x + (tile*64 + r)*64 + c4);
        uint32_t h01 = pack_hi(v.x, v.y), h23 = pack_hi(v.z, v.w);
        uint32_t l01 = pack_lo(v.x, v.y, h01), l23 = pack_lo(v.z, v.w, h23);
        *reinterpret_cast<uint2*>(smn + QK2_XH + r*STRB + c4*2) = make_uint2(h01, h23);
        *reinterpret_cast<uint2*>(smn + QK2_XL + r*STRB + c4*2) = make_uint2(l01, l23);
    }
    {
        const float* const Wm[3] = {Wq, Wk, Wv};
        #pragma unroll
        for (int m = 0; m < 3; m++) {
            const float* W = Wm[m];
            const int base = QK2_WB + m*(2*64*STRB);
            #pragma unroll
            for (int i = tid; i < 1024; i += 128) {
                const int r = i >> 4, c4 = (i & 15) << 2;
                float4 v = *reinterpret_cast<const float4*>(W + r*768 + head*64 + c4);
                uint32_t h01 = pack_hi(v.x, v.y), h23 = pack_hi(v.z, v.w);
                uint32_t l01 = pack_lo(v.x, v.y, h01), l23 = pack_lo(v.z, v.w, h23);
                *reinterpret_cast<uint2*>(smn + base + r*STRB + c4*2) = make_uint2(h01, h23);
                *reinterpret_cast<uint2*>(smn + base + 64*STRB + r*STRB + c4*2) = make_uint2(l01, l23);
            }
        }
    }
    __syncthreads();

    uint32_t ah[4][4], al[4][4];
    #pragma unroll
    for (int kc = 0; kc < 4; kc++) {
        const uint32_t aoff = (uint32_t)((wid*16 + qrow_l)*STRB + (kc*16 + qch*8)*2);
        ldx4(ah[kc], sb + QK2_XH + aoff);
        ldx4(al[kc], sb + QK2_XL + aoff);
    }

    const int rg0 = tile*64 + wid*16 + g;
    const int bi  = rg0 >> 11;
    const int si0 = rg0 & (SEQ-1);
    const int bh  = bi*NH + head;
    const float* const Bm[3] = {bq, bk, bv};

    #pragma unroll
    for (int m = 0; m < 3; m++) {
        const uint32_t whb = sb + QK2_WB + m*(2*64*STRB);
        const uint32_t wlb = whb + 64*STRB;
        float dacc[8][4];
        #pragma unroll
        for (int j = 0; j < 8; j++)
            #pragma unroll
            for (int e = 0; e < 4; e++) dacc[j][e] = 0.f;

        #pragma unroll
        for (int kc = 0; kc < 4; kc++) {
            #pragma unroll
            for (int jdp = 0; jdp < 4; jdp++) {
                const uint32_t voff = (uint32_t)((kc*16 + vrow_l)*STRB + ((2*jdp + vch)*8)*2);
                uint32_t bhf[4], blf[4];
                ldx4t(bhf, whb + voff);
                ldx4t(blf, wlb + voff);
                mma16816(dacc[2*jdp],   ah[kc], bhf[0], bhf[1]);
                mma16816(dacc[2*jdp+1], ah[kc], bhf[2], bhf[3]);
                mma16816(dacc[2*jdp],   ah[kc], blf[0], blf[1]);
                mma16816(dacc[2*jdp+1], ah[kc], blf[2], blf[3]);
                mma16816(dacc[2*jdp],   al[kc], bhf[0], bhf[1]);
                mma16816(dacc[2*jdp+1], al[kc], bhf[2], bhf[3]);
            }
        }

        const float* bias = Bm[m] + head*64;
        #pragma unroll
        for (int jd = 0; jd < 8; jd++) {
            const int col = jd*8 + 2*t;
            const float b0 = bias[col], b1 = bias[col+1];
            const float v0 = dacc[jd][0] + b0, v1 = dacc[jd][1] + b1;
            const float v2 = dacc[jd][2] + b0, v3 = dacc[jd][3] + b1;
            const int idx0 = (bh*SEQ + si0)*HD + col;
            const int idx8 = idx0 + 8*HD;
            if (m == 0) {
                *reinterpret_cast<uint32_t*>(g_Q + idx0) = packh2(v0, v1);
                *reinterpret_cast<uint32_t*>(g_Q + idx8) = packh2(v2, v3);
            } else if (m == 1) {
                uint32_t h01 = packh2(v0, v1), h23 = packh2(v2, v3);
                *reinterpret_cast<uint32_t*>(g_Kh + idx0) = h01;
                *reinterpret_cast<uint32_t*>(g_Kl + idx0) = packh2_lo(v0, v1, h01);
                *reinterpret_cast<uint32_t*>(g_Kh + idx8) = h23;
                *reinterpret_cast<uint32_t*>(g_Kl + idx8) = packh2_lo(v2, v3, h23);
            } else {
                uint32_t h01 = pack_hi(v0, v1), h23 = pack_hi(v2, v3);
                *reinterpret_cast<uint32_t*>(g_Vh + idx0) = h01;
                *reinterpret_cast<uint32_t*>(g_Vl + idx0) = pack_lo(v0, v1, h01);
                *reinterpret_cast<uint32_t*>(g_Vh + idx8) = h23;
                *reinterpret_cast<uint32_t*>(g_Vl + idx8) = pack_lo(v2, v3, h23);
            }
        }
    }
}

// ---------------------------------------------------------------------------
// Kernel 2: flash attention with SPLIT-K (R15, unchanged).
// ---------------------------------------------------------------------------
#define SM_ITEM 0
#define SM_Q    16
#define SM_KH0  (SM_Q + 128*STRB)
#define SM_KL0  (SM_KH0 + 64*STRB)
#define SM_VH0  (SM_KL0 + 64*STRB)
#define SM_VL0  (SM_VH0 + 64*STRB)
#define SM_KH1  (SM_VL0 + 64*STRB)
#define SM_KL1  (SM_KH1 + 64*STRB)
#define SM_VH1  (SM_KL1 + 64*STRB)
#define SM_VL1  (SM_VH1 + 64*STRB)
#define ATTN_SMEM_BYTES (SM_VL1 + 64*STRB)

__global__ __launch_bounds__(256, 2) void attn_kernel()
{
    extern __shared__ __align__(16) char smn[];
    const uint32_t sb = smem_u32(smn);
    const int tid  = threadIdx.x;
    const int wid  = tid >> 5;
    const int lane = tid & 31;
    const int g    = lane >> 2;
    const int t    = lane & 3;
    int* itp = reinterpret_cast<int*>(smn + SM_ITEM);

    const int qrow_l = (lane & 15);
    const int qch    = (lane >> 4);
    const int krow_l = ((lane >> 4) & 1)*8 + (lane & 7);
    const int kch    = (lane >> 3) & 1;
    const int vrow_l = ((lane >> 3) & 1)*8 + (lane & 7);
    const int vch    = (lane >> 4) & 1;

    for (;;) {
        __syncthreads();
        if (tid == 0) *itp = atomicAdd(&g_counter, 1);
        __syncthreads();
        const int it = *itp;
        if (it >= N_ITEMS) return;

        const int p    = it >> 1;
        const int half = it & 1;
        const int qr = p / 24;
        const int qx = 15 - qr;
        const int bh = p - qr * 24;
        const int qb  = qx * 128;
        const int off = bh * SEQ * HD;
        const int nkt = 2*qx + 2;
        const int nA  = nkt >> 1;
        const int kt0 = half ? nA  : 0;
        const int kt1 = half ? nkt : nA;
        const int slot = p;

        #pragma unroll
        for (int i = tid; i < 1024; i += 256) {
            const int r = i >> 3, c = i & 7;
            cp16(smn + SM_Q + r*STRB + c*16, g_Q + off + (qb + r)*64 + c*8);
        }
        {
            const int kb0 = kt0 * 64;
            #pragma unroll
            for (int i = tid; i < 512; i += 256) {
                const int r = i >> 3, c = i & 7;
                cp16(smn + SM_KH0 + r*STRB + c*16, g_Kh + off + (kb0 + r)*64 + c*8);
                cp16(smn + SM_KL0 + r*STRB + c*16, g_Kl + off + (kb0 + r)*64 + c*8);
                cp16(smn + SM_VH0 + r*STRB + c*16, g_Vh + off + (kb0 + r)*64 + c*8);
                cp16(smn + SM_VL0 + r*STRB + c*16, g_Vl + off + (kb0 + r)*64 + c*8);
            }
        }
        cp_commit();

        float dacc[8][4];
        #pragma unroll
        for (int j = 0; j < 8; j++)
            #pragma unroll
            for (int e = 0; e < 4; e++) dacc[j][e] = 0.f;
        float lsum0 = 0.f, lsum8 = 0.f;

        const int row0 = qb + wid*16 + g;
        const int row8 = row0 + 8;

        for (int kt = kt0; kt < kt1; ++kt) {
            const int kb  = kt * 64;
            const int buf = (kt - kt0) & 1;
            cp_wait0();
            __syncthreads();

            if (kt + 1 < kt1) {
                const int nkb = kb + 64;
                const uint32_t okh = buf ? SM_KH0 : SM_KH1;
                const uint32_t okl = buf ? SM_KL0 : SM_KL1;
                const uint32_t ovh = buf ? SM_VH0 : SM_VH1;
                const uint32_t ovl = buf ? SM_VL0 : SM_VL1;
                #pragma unroll
                for (int i = tid; i < 512; i += 256) {
                    const int r = i >> 3, c = i & 7;
                    cp16(smn + okh + r*STRB + c*16, g_Kh + off + (nkb + r)*64 + c*8);
                    cp16(smn + okl + r*STRB + c*16, g_Kl + off + (nkb + r)*64 + c*8);
                    cp16(smn + ovh + r*STRB + c*16, g_Vh + off + (nkb + r)*64 + c*8);
                    cp16(smn + ovl + r*STRB + c*16, g_Vl + off + (nkb + r)*64 + c*8);
                }
            }
            cp_commit();

            const uint32_t bkh = sb + (buf ? SM_KH1 : SM_KH0);
            const uint32_t bkl = sb + (buf ? SM_KL1 : SM_KL0);
            const uint32_t bvh = sb + (buf ? SM_VH1 : SM_VH0);
            const uint32_t bvl = sb + (buf ? SM_VL1 : SM_VL0);

            float sacc[8][4];
            #pragma unroll
            for (int j = 0; j < 8; j++)
                #pragma unroll
                for (int e = 0; e < 4; e++) sacc[j][e] = 0.f;

            #pragma unroll
            for (int ks = 0; ks < 4; ks++) {
                uint32_t qh[4];
                const uint32_t qoff = (uint32_t)((wid*16 + qrow_l)*STRB + (ks*16 + qch*8)*2);
                ldx4(qh, sb + SM_Q + qoff);
                #pragma unroll
                for (int jp = 0; jp < 4; jp++) {
                    const uint32_t koff = (uint32_t)((jp*16 + krow_l)*STRB + (ks*16 + kch*8)*2);
                    uint32_t khb[4], klb[4];
                    ldx4(khb, bkh + koff);
                    ldx4(klb, bkl + koff);
                    mmah(sacc[2*jp],   qh, khb[0], khb[1]);
                    mmah(sacc[2*jp+1], qh, khb[2], khb[3]);
                    mmah(sacc[2*jp],   qh, klb[0], klb[1]);
                    mmah(sacc[2*jp+1], qh, klb[2], klb[3]);
                }
            }

            uint32_t ph[4][4], pl[4][4];
            #pragma unroll
            for (int jn = 0; jn < 8; jn++) {
                const int col = kb + jn*8 + 2*t;
                float v0 = sacc[jn][0], v1 = sacc[jn][1];
                float v2 = sacc[jn][2], v3 = sacc[jn][3];
                if (col     > row0 || v0 == 0.0f) v0 = NEGV;
                if (col + 1 > row0 || v1 == 0.0f) v1 = NEGV;
                if (col     > row8 || v2 == 0.0f) v2 = NEGV;
                if (col + 1 > row8 || v3 == 0.0f) v3 = NEGV;
                const float p0 = __expf(v0);
                const float p1 = __expf(v1);
                const float p2 = __expf(v2);
                const float p3 = __expf(v3);
                lsum0 += p0 + p1;
                lsum8 += p2 + p3;
                const int kc = jn >> 1, hf = jn & 1;
                uint32_t h01 = pack_hi(p0, p1);
                uint32_t h23 = pack_hi(p2, p3);
                ph[kc][hf*2 + 0] = h01;
                ph[kc][hf*2 + 1] = h23;
                pl[kc][hf*2 + 0] = pack_lo(p0, p1, h01);
                pl[kc][hf*2 + 1] = pack_lo(p2, p3, h23);
            }

            #pragma unroll
            for (int kc = 0; kc < 4; kc++) {
                #pragma unroll
                for (int jdp = 0; jdp < 4; jdp++) {
                    const uint32_t voff =
                        (uint32_t)((kc*16 + vrow_l)*STRB + ((2*jdp + vch)*8)*2);
                    uint32_t vhb[4], vlb[4];
                    ldx4t(vhb, bvh + voff);
                    ldx4t(vlb, bvl + voff);
                    mma16816(dacc[2*jdp],   ph[kc], vhb[0], vhb[1]);
                    mma16816(dacc[2*jdp+1], ph[kc], vhb[2], vhb[3]);
                    mma16816(dacc[2*jdp],   ph[kc], vlb[0], vlb[1]);
                    mma16816(dacc[2*jdp+1], ph[kc], vlb[2], vlb[3]);
                    mma16816(dacc[2*jdp],   pl[kc], vhb[0], vhb[1]);
                    mma16816(dacc[2*jdp+1], pl[kc], vhb[2], vhb[3]);
                }
            }
        }

        // ---- quad-reduce this half's row sums ----
        #pragma unroll
        for (int o_ = 1; o_ < 4; o_ <<= 1) {
            lsum0 += __shfl_xor_sync(0xffffffffu, lsum0, o_);
            lsum8 += __shfl_xor_sync(0xffffffffu, lsum8, o_);
        }
        const int rloc0 = wid*16 + g;
        const int rloc8 = rloc0 + 8;
        float* pacc = g_Pacc + slot*(128*64);

        if (half == 0) {
            #pragma unroll
            for (int jd = 0; jd < 8; jd++) {
                const int col = jd*8 + 2*t;
                *reinterpret_cast<float2*>(pacc + rloc0*64 + col) =
                    make_float2(dacc[jd][0], dacc[jd][1]);
                *reinterpret_cast<float2*>(pacc + rloc8*64 + col) =
                    make_float2(dacc[jd][2], dacc[jd][3]);
            }
            if (t == 0) {
                g_Plsum[slot*128 + rloc0] = lsum0;
                g_Plsum[slot*128 + rloc8] = lsum8;
            }
            __threadfence();
            __syncthreads();
            if (tid == 0) atomicExch(&g_flag[slot], 1);
        } else {
            if (tid == 0) { while (atomicAdd(&g_flag[slot], 0) == 0) { } }
            __syncthreads();
            __threadfence();
            lsum0 += g_Plsum[slot*128 + rloc0];
            lsum8 += g_Plsum[slot*128 + rloc8];
            const float inv0 = 1.0f / lsum0;
            const float inv8 = 1.0f / lsum8;
            #pragma unroll
            for (int jd = 0; jd < 8; jd++) {
                const int col = jd*8 + 2*t;
                float2 a0 = *reinterpret_cast<float2*>(pacc + rloc0*64 + col);
                float2 a8 = *reinterpret_cast<float2*>(pacc + rloc8*64 + col);
                const float v0 = (dacc[jd][0] + a0.x)*inv0;
                const float v1 = (dacc[jd][1] + a0.y)*inv0;
                const float v2 = (dacc[jd][2] + a8.x)*inv8;
                const float v3 = (dacc[jd][3] + a8.y)*inv8;
                uint32_t h01 = pack_hi(v0, v1), l01 = pack_lo(v0, v1, h01);
                uint32_t h23 = pack_hi(v2, v3), l23 = pack_lo(v2, v3, h23);
                *reinterpret_cast<uint32_t*>(g_Ohi + off + row0*64 + col) = h01;
                *reinterpret_cast<uint32_t*>(g_Olo + off + row0*64 + col) = l01;
                *reinterpret_cast<uint32_t*>(g_Ohi + off + row8*64 + col) = h23;
                *reinterpret_cast<uint32_t*>(g_Olo + off + row8*64 + col) = l23;
            }
        }
    }
}

// ---------------------------------------------------------------------------
// Kernel 3: HMMA output projection (bf16 3-term).  (R12/R15, unchanged)
// ---------------------------------------------------------------------------
#define PJ_OH0 0
#define PJ_OL0 (32*STRB)
#define PJ_WH0 (2*32*STRB)
#define PJ_WL0 (2*32*STRB + 64*STRB)
#define PJ_BUF (2*32*STRB + 2*64*STRB)
#define PROJ_SMEM (2*PJ_BUF)

__global__ __launch_bounds__(64) void proj_kernel(
    const float* __restrict__ bo, float* __restrict__ out)
{
    extern __shared__ __align__(16) char smn[];
    const uint32_t sb = smem_u32(smn);
    const int blk  = blockIdx.x;
    const int tid  = threadIdx.x;
    const int wid  = tid >> 5;
    const int lane = tid & 31;
    const int g    = lane >> 2;
    const int t    = lane & 3;
    const int qrow_l = lane & 15;
    const int qch    = lane >> 4;
    const int vrow_l = ((lane >> 3) & 1)*8 + (lane & 7);
    const int vch    = (lane >> 4) & 1;

    const int rgb   = blk*32;
    const int bi    = rgb >> 11;
    const int sbase = rgb & (SEQ-1);

    #pragma unroll
    for (int i = tid; i < 256; i += 64) {
        const int r = i >> 3, c = i & 7;
        const int gidx = ((bi*NH + 0)*SEQ + sbase + r)*64 + c*8;
        cp16(smn + PJ_OH0 + r*STRB + c*16, g_Ohi + gidx);
        cp16(smn + PJ_OL0 + r*STRB + c*16, g_Olo + gidx);
    }
    #pragma unroll
    for (int i = tid; i < 512; i += 64) {
        const int r = i >> 3, c = i & 7;
        cp16(smn + PJ_WH0 + r*STRB + c*16, g_Woh + r*64 + c*8);
        cp16(smn + PJ_WL0 + r*STRB + c*16, g_Wol + r*64 + c*8);
    }
    cp_commit();

    float dacc[8][4];
    #pragma unroll
    for (int j = 0; j < 8; j++)
        #pragma unroll
        for (int e = 0; e < 4; e++) dacc[j][e] = 0.f;

    for (int h = 0; h < NH; ++h) {
        const int buf = h & 1;
        cp_wait0();
        __syncthreads();

        if (h + 1 < NH) {
            const int nb = (buf ^ 1) * PJ_BUF;
            const int nh = h + 1;
            #pragma unroll
            for (int i = tid; i < 256; i += 64) {
                const int r = i >> 3, c = i & 7;
                const int gidx = ((bi*NH + nh)*SEQ + sbase + r)*64 + c*8;
                cp16(smn + nb + PJ_OH0 + r*STRB + c*16, g_Ohi + gidx);
                cp16(smn + nb + PJ_OL0 + r*STRB + c*16, g_Olo + gidx);
            }
            #pragma unroll
            for (int i = tid; i < 512; i += 64) {
                const int r = i >> 3, c = i & 7;
                cp16(smn + nb + PJ_WH0 + r*STRB + c*16, g_Woh + (nh*64 + r)*64 + c*8);
                cp16(smn + nb + PJ_WL0 + r*STRB + c*16, g_Wol + (nh*64 + r)*64 + c*8);
            }
        }
        cp_commit();

        const uint32_t ohb = sb + buf*PJ_BUF + PJ_OH0;
        const uint32_t olb = sb + buf*PJ_BUF + PJ_OL0;
        const uint32_t whb = sb + buf*PJ_BUF + PJ_WH0;
        const uint32_t wlb = sb + buf*PJ_BUF + PJ_WL0;

        #pragma unroll
        for (int kc = 0; kc < 4; kc++) {
            uint32_t ah[4], al[4];
            const uint32_t aoff = (uint32_t)((wid*16 + qrow_l)*STRB + (kc*16 + qch*8)*2);
            ldx4(ah, ohb + aoff);
            ldx4(al, olb + aoff);
            #pragma unroll
            for (int jdp = 0; jdp < 4; jdp++) {
                const uint32_t voff = (uint32_t)((kc*16 + vrow_l)*STRB + ((2*jdp + vch)*8)*2);
                uint32_t bhf[4], blf[4];
                ldx4t(bhf, whb + voff);
                ldx4t(blf, wlb + voff);
                mma16816(dacc[2*jdp],   ah, bhf[0], bhf[1]);
                mma16816(dacc[2*jdp+1], ah, bhf[2], bhf[3]);
                mma16816(dacc[2*jdp],   ah, blf[0], blf[1]);
                mma16816(dacc[2*jdp+1], ah, blf[2], blf[3]);
                mma16816(dacc[2*jdp],   al, bhf[0], bhf[1]);
                mma16816(dacc[2*jdp+1], al, bhf[2], bhf[3]);
            }
        }
    }

    const int row0 = rgb + wid*16 + g;
    const int row8 = row0 + 8;
    #pragma unroll
    for (int jd = 0; jd < 8; jd++) {
        const int col = jd*8 + 2*t;
        const float b0 = bo[col], b1 = bo[col+1];
        *reinterpret_cast<float2*>(out + row0*64 + col) =
            make_float2(dacc[jd][0] + b0, dacc[jd][1] + b1);
        *reinterpret_cast<float2*>(out + row8*64 + col) =
            make_float2(dacc[jd][2] + b0, dacc[jd][3] + b1);
    }
}

// ---------------------------------------------------------------------------
extern "C" void kernel_launch(void* const* d_in, const int* in_sizes, int n_in,
                              void* d_out, int out_size)
{
    (void)in_sizes; (void)n_in; (void)out_size;
    const float* x  = (const float*)d_in[0];
    const float* Wq = (const float*)d_in[1];
    const float* bq = (const float*)d_in[2];
    const float* Wk = (const float*)d_in[3];
    const float* bk = (const float*)d_in[4];
    const float* Wv = (const float*)d_in[5];
    const float* bv = (const float*)d_in[6];
    const float* Wo = (const float*)d_in[7];
    const float* bo = (const float*)d_in[8];
    float* out = (float*)d_out;

    cudaFuncSetAttribute(attn_kernel,
                         cudaFuncAttributeMaxDynamicSharedMemorySize,
                         ATTN_SMEM_BYTES);
    cudaFuncSetAttribute(qkv_kernel,
                         cudaFuncAttributeMaxDynamicSharedMemorySize,
                         QKV2_SMEM);
    cudaFuncSetAttribute(proj_kernel,
                         cudaFuncAttributeMaxDynamicSharedMemorySize,
                         PROJ_SMEM);

    qkv_kernel<<<dim3(64, 12), 128, QKV2_SMEM>>>(x, Wq, bq, Wk, bk, Wv, bv, Wo);
    attn_kernel<<<N_CTAS, 256, ATTN_SMEM_BYTES>>>();
    proj_kernel<<<128, 64, PROJ_SMEM>>>(bo, out);
}